// round 3
// baseline (speedup 1.0000x reference)
#include <cuda_runtime.h>
#include <cstdint>
#include <math.h>

#define JAX_PARTITIONABLE 1

#define Bb 16
#define Ss 512
#define Dd 768
#define Kc 8192
#define Hh 8
#define Ll 6
#define FFd 2048
#define NTOK 8192
#define DH 96
#define NEGB (-1e9f)

// ---------------- scratch (device globals; no allocation allowed) ----------------
__device__ float g_mem  [NTOK * Dd];        // z_e (cross-attn memory)
__device__ float g_h    [NTOK * Dd];        // residual stream
__device__ float g_tmp  [NTOK * Dd];        // pre-LN residual sum
__device__ float g_attno[NTOK * Dd];        // attention output (pre-proj)
__device__ float g_qkv  [NTOK * 3 * Dd];
__device__ float g_ffbuf[NTOK * FFd];
__device__ float g_scores[(size_t)Bb * Hh * Ss * Ss];
__device__ float g_dist [(size_t)NTOK * Kc];
__device__ float g_xnorm[NTOK];
__device__ float g_cnorm[Kc];
__device__ int   g_pad  [NTOK];
__device__ int   g_enc  [NTOK];

// ---------------- reductions ----------------
__device__ __forceinline__ float blockReduceSum256(float v, float* sb) {
    int tid = threadIdx.x;
    #pragma unroll
    for (int o = 16; o > 0; o >>= 1) v += __shfl_down_sync(0xffffffffu, v, o);
    if ((tid & 31) == 0) sb[tid >> 5] = v;
    __syncthreads();
    float s = 0.f;
    if (tid < 32) {
        s = (tid < (int)(blockDim.x >> 5)) ? sb[tid] : 0.f;
        #pragma unroll
        for (int o = 16; o > 0; o >>= 1) s += __shfl_down_sync(0xffffffffu, s, o);
        if (tid == 0) sb[0] = s;
    }
    __syncthreads();
    float r = sb[0];
    __syncthreads();
    return r;
}

__device__ __forceinline__ float blockReduceMax(float v, float* sb) {
    int tid = threadIdx.x;
    #pragma unroll
    for (int o = 16; o > 0; o >>= 1) v = fmaxf(v, __shfl_down_sync(0xffffffffu, v, o));
    if ((tid & 31) == 0) sb[tid >> 5] = v;
    __syncthreads();
    float s = -3.4e38f;
    if (tid < 32) {
        s = (tid < (int)(blockDim.x >> 5)) ? sb[tid] : -3.4e38f;
        #pragma unroll
        for (int o = 16; o > 0; o >>= 1) s = fmaxf(s, __shfl_down_sync(0xffffffffu, s, o));
        if (tid == 0) sb[0] = s;
    }
    __syncthreads();
    float r = sb[0];
    __syncthreads();
    return r;
}

// ---------------- row stats ----------------
__global__ void __launch_bounds__(256) rowstat_x(const float* __restrict__ x) {
    __shared__ float sb[32];
    int row = blockIdx.x, tid = threadIdx.x;
    float v[3];
    #pragma unroll
    for (int i = 0; i < 3; i++) v[i] = x[(size_t)row * Dd + tid + i * 256];
    float ss = v[0]*v[0] + v[1]*v[1] + v[2]*v[2];
    ss = blockReduceSum256(ss, sb);
    int pad = (sqrtf(ss) <= 1e-6f) ? 1 : 0;
    if (tid == 0) { g_pad[row] = pad; g_xnorm[row] = pad ? 0.f : ss; }
    #pragma unroll
    for (int i = 0; i < 3; i++)
        g_mem[(size_t)row * Dd + tid + i * 256] = pad ? 0.f : v[i];
}

__global__ void __launch_bounds__(256) rowstat_cb(const float* __restrict__ cb) {
    __shared__ float sb[32];
    int row = blockIdx.x, tid = threadIdx.x;
    float ss = 0.f;
    #pragma unroll
    for (int i = 0; i < 3; i++) {
        float v = cb[(size_t)row * Dd + tid + i * 256];
        ss += v * v;
    }
    ss = blockReduceSum256(ss, sb);
    if (tid == 0) g_cnorm[row] = ss;
}

// ---------------- generic NT SGEMM: C = epi(sum_k A[m,k]*W[n,k]) ----------------
// mode 0: +bias   mode 1: relu(+bias)   mode 2: +bias+resid   mode 3: (rn[m]+cn[n]) - 2*acc
__global__ void __launch_bounds__(256) sgemm_nt(
    const float* __restrict__ A, int lda,
    const float* __restrict__ W, int ldw,
    const float* __restrict__ bias,
    const float* __restrict__ resid, int ldr,
    const float* __restrict__ rnorm, const float* __restrict__ cnorm,
    float* __restrict__ C, int ldc, int K, int mode)
{
    __shared__ float As[16][132];
    __shared__ float Ws[16][132];
    const int bm = blockIdx.y * 128, bn = blockIdx.x * 128;
    const int tid = threadIdx.x;
    const int tx = tid & 15, ty = tid >> 4;
    float acc[8][8];
    #pragma unroll
    for (int i = 0; i < 8; i++)
        #pragma unroll
        for (int j = 0; j < 8; j++) acc[i][j] = 0.f;

    for (int k0 = 0; k0 < K; k0 += 16) {
        #pragma unroll
        for (int u = 0; u < 2; u++) {
            int f = tid + u * 256;
            int row = f >> 2;
            int c4 = (f & 3) << 2;
            float4 a = *(const float4*)(A + (size_t)(bm + row) * lda + k0 + c4);
            As[c4 + 0][row] = a.x; As[c4 + 1][row] = a.y;
            As[c4 + 2][row] = a.z; As[c4 + 3][row] = a.w;
            float4 w = *(const float4*)(W + (size_t)(bn + row) * ldw + k0 + c4);
            Ws[c4 + 0][row] = w.x; Ws[c4 + 1][row] = w.y;
            Ws[c4 + 2][row] = w.z; Ws[c4 + 3][row] = w.w;
        }
        __syncthreads();
        #pragma unroll
        for (int kk = 0; kk < 16; kk++) {
            float a[8], b[8];
            *(float4*)(a)     = *(const float4*)&As[kk][ty * 8];
            *(float4*)(a + 4) = *(const float4*)&As[kk][ty * 8 + 4];
            *(float4*)(b)     = *(const float4*)&Ws[kk][tx * 8];
            *(float4*)(b + 4) = *(const float4*)&Ws[kk][tx * 8 + 4];
            #pragma unroll
            for (int i = 0; i < 8; i++)
                #pragma unroll
                for (int j = 0; j < 8; j++)
                    acc[i][j] = fmaf(a[i], b[j], acc[i][j]);
        }
        __syncthreads();
    }

    #pragma unroll
    for (int i = 0; i < 8; i++) {
        int row = bm + ty * 8 + i;
        #pragma unroll
        for (int jj = 0; jj < 8; jj += 4) {
            int col = bn + tx * 8 + jj;
            float4 v = make_float4(acc[i][jj], acc[i][jj+1], acc[i][jj+2], acc[i][jj+3]);
            if (mode == 3) {
                float xn = rnorm[row];
                v.x = (xn + cnorm[col + 0]) - 2.f * v.x;
                v.y = (xn + cnorm[col + 1]) - 2.f * v.y;
                v.z = (xn + cnorm[col + 2]) - 2.f * v.z;
                v.w = (xn + cnorm[col + 3]) - 2.f * v.w;
            } else {
                if (bias) {
                    float4 bv = *(const float4*)(bias + col);
                    v.x += bv.x; v.y += bv.y; v.z += bv.z; v.w += bv.w;
                }
                if (mode == 2) {
                    float4 r = *(const float4*)(resid + (size_t)row * ldr + col);
                    v.x += r.x; v.y += r.y; v.z += r.z; v.w += r.w;
                }
                if (mode == 1) {
                    v.x = fmaxf(v.x, 0.f); v.y = fmaxf(v.y, 0.f);
                    v.z = fmaxf(v.z, 0.f); v.w = fmaxf(v.w, 0.f);
                }
            }
            *(float4*)(C + (size_t)row * ldc + col) = v;
        }
    }
}

// ---------------- attention: scores ----------------
__global__ void __launch_bounds__(256) attn_scores(int causal) {
    __shared__ float Qs[32][68];
    __shared__ float Ks[32][68];
    int kt = blockIdx.x, qt = blockIdx.y, bh = blockIdx.z;
    int b = bh >> 3, h = bh & 7;
    const float* __restrict__ Qb = g_qkv + (size_t)b * Ss * 3 * Dd + h * DH;
    const float* __restrict__ Kb = Qb + Dd;
    int tid = threadIdx.x, tx = tid & 15, ty = tid >> 4;
    float acc[4][4];
    #pragma unroll
    for (int i = 0; i < 4; i++)
        #pragma unroll
        for (int j = 0; j < 4; j++) acc[i][j] = 0.f;

    for (int k0 = 0; k0 < DH; k0 += 32) {
        #pragma unroll
        for (int u = 0; u < 2; u++) {
            int f = tid + u * 256;
            int row = f >> 3;
            int c4 = (f & 7) << 2;
            float4 q = *(const float4*)(Qb + (size_t)(qt * 64 + row) * (3 * Dd) + k0 + c4);
            Qs[c4 + 0][row] = q.x; Qs[c4 + 1][row] = q.y;
            Qs[c4 + 2][row] = q.z; Qs[c4 + 3][row] = q.w;
            float4 kv = *(const float4*)(Kb + (size_t)(kt * 64 + row) * (3 * Dd) + k0 + c4);
            Ks[c4 + 0][row] = kv.x; Ks[c4 + 1][row] = kv.y;
            Ks[c4 + 2][row] = kv.z; Ks[c4 + 3][row] = kv.w;
        }
        __syncthreads();
        #pragma unroll
        for (int kk = 0; kk < 32; kk++) {
            float a[4], bfr[4];
            *(float4*)a   = *(const float4*)&Qs[kk][ty * 4];
            *(float4*)bfr = *(const float4*)&Ks[kk][tx * 4];
            #pragma unroll
            for (int i = 0; i < 4; i++)
                #pragma unroll
                for (int j = 0; j < 4; j++)
                    acc[i][j] = fmaf(a[i], bfr[j], acc[i][j]);
        }
        __syncthreads();
    }

    const float scale = 9.797958971132712f;  // np.float32(np.sqrt(96))
    #pragma unroll
    for (int i = 0; i < 4; i++) {
        int q = qt * 64 + ty * 4 + i;
        float4 v;
        float* pv = &v.x;
        #pragma unroll
        for (int j = 0; j < 4; j++) {
            int k = kt * 64 + tx * 4 + j;
            float s = acc[i][j] / scale;
            if (causal && q > k) s += NEGB;
            if (g_pad[b * Ss + k]) s += NEGB;
            pv[j] = s;
        }
        *(float4*)(g_scores + ((size_t)bh * Ss + q) * Ss + kt * 64 + tx * 4) = v;
    }
}

// ---------------- softmax over rows of 512 (vectorized) ----------------
__global__ void __launch_bounds__(128) softmax512() {
    __shared__ float sb[32];
    float* p = g_scores + (size_t)blockIdx.x * Ss;
    int tid = threadIdx.x;
    float4 v = *(const float4*)(p + tid * 4);
    float m = fmaxf(fmaxf(v.x, v.y), fmaxf(v.z, v.w));
    m = blockReduceMax(m, sb);
    float4 e;
    e.x = expf(v.x - m); e.y = expf(v.y - m);
    e.z = expf(v.z - m); e.w = expf(v.w - m);
    float s = e.x + e.y + e.z + e.w;
    s = blockReduceSum256(s, sb);
    float inv = 1.0f / s;
    e.x *= inv; e.y *= inv; e.z *= inv; e.w *= inv;
    *(float4*)(p + tid * 4) = e;
}

// ---------------- attention: P @ V ----------------
__global__ void __launch_bounds__(256) attn_av() {
    __shared__ float Ps[16][68];
    __shared__ float Vs[16][96];
    int qt = blockIdx.x, bh = blockIdx.y;
    int b = bh >> 3, h = bh & 7;
    const float* __restrict__ P = g_scores + (size_t)bh * Ss * Ss + (size_t)qt * 64 * Ss;
    const float* __restrict__ Vb = g_qkv + (size_t)b * Ss * 3 * Dd + 2 * Dd + h * DH;
    int tid = threadIdx.x, tx = tid & 15, ty = tid >> 4;
    float acc[4][6];
    #pragma unroll
    for (int i = 0; i < 4; i++)
        #pragma unroll
        for (int j = 0; j < 6; j++) acc[i][j] = 0.f;

    for (int k0 = 0; k0 < Ss; k0 += 16) {
        {
            int row = tid >> 2;
            int c4 = (tid & 3) << 2;
            float4 pv = *(const float4*)(P + (size_t)row * Ss + k0 + c4);
            Ps[c4 + 0][row] = pv.x; Ps[c4 + 1][row] = pv.y;
            Ps[c4 + 2][row] = pv.z; Ps[c4 + 3][row] = pv.w;
        }
        #pragma unroll
        for (int u = 0; u < 6; u++) {
            int f = tid + u * 256;
            int r = f / 96, c = f - r * 96;
            Vs[r][c] = Vb[(size_t)(k0 + r) * (3 * Dd) + c];
        }
        __syncthreads();
        #pragma unroll
        for (int kk = 0; kk < 16; kk++) {
            float a[4];
            *(float4*)a = *(const float4*)&Ps[kk][ty * 4];
            float bf[6];
            #pragma unroll
            for (int j = 0; j < 6; j++) bf[j] = Vs[kk][tx * 6 + j];
            #pragma unroll
            for (int i = 0; i < 4; i++)
                #pragma unroll
                for (int j = 0; j < 6; j++)
                    acc[i][j] = fmaf(a[i], bf[j], acc[i][j]);
        }
        __syncthreads();
    }
    #pragma unroll
    for (int i = 0; i < 4; i++) {
        int q = qt * 64 + ty * 4 + i;
        #pragma unroll
        for (int j = 0; j < 6; j++)
            g_attno[(size_t)(b * Ss + q) * Dd + h * DH + tx * 6 + j] = acc[i][j];
    }
}

// ---------------- layernorm: g_h = LN(g_tmp)*g + b ----------------
__global__ void __launch_bounds__(256) layernorm(const float* __restrict__ gam,
                                                 const float* __restrict__ bet) {
    __shared__ float sb[32];
    int row = blockIdx.x, tid = threadIdx.x;
    const float* x = g_tmp + (size_t)row * Dd;
    float v[3];
    #pragma unroll
    for (int i = 0; i < 3; i++) v[i] = x[tid + i * 256];
    float s = v[0] + v[1] + v[2];
    s = blockReduceSum256(s, sb);
    float mean = s / 768.0f;
    float d2 = 0.f;
    #pragma unroll
    for (int i = 0; i < 3; i++) { float d = v[i] - mean; d2 += d * d; }
    d2 = blockReduceSum256(d2, sb);
    float var = d2 / 768.0f;
    float inv = 1.0f / sqrtf(var + 1e-5f);
    #pragma unroll
    for (int i = 0; i < 3; i++) {
        int c = tid + i * 256;
        g_h[(size_t)row * Dd + c] = (v[i] - mean) * inv * gam[c] + bet[c];
    }
}

// ---------------- threefry2x32 (JAX-exact) ----------------
__device__ __forceinline__ uint32_t rotl32(uint32_t x, int d) {
    return (x << d) | (x >> (32 - d));
}
__device__ void threefry2x32(uint32_t k0, uint32_t k1, uint32_t x0, uint32_t x1,
                             uint32_t& o0, uint32_t& o1) {
    uint32_t k2 = k0 ^ k1 ^ 0x1BD11BDAu;
    x0 += k0; x1 += k1;
    x0 += x1; x1 = rotl32(x1, 13); x1 ^= x0;
    x0 += x1; x1 = rotl32(x1, 15); x1 ^= x0;
    x0 += x1; x1 = rotl32(x1, 26); x1 ^= x0;
    x0 += x1; x1 = rotl32(x1, 6);  x1 ^= x0;
    x0 += k1; x1 += k2 + 1u;
    x0 += x1; x1 = rotl32(x1, 17); x1 ^= x0;
    x0 += x1; x1 = rotl32(x1, 29); x1 ^= x0;
    x0 += x1; x1 = rotl32(x1, 16); x1 ^= x0;
    x0 += x1; x1 = rotl32(x1, 24); x1 ^= x0;
    x0 += k2; x1 += k0 + 2u;
    x0 += x1; x1 = rotl32(x1, 13); x1 ^= x0;
    x0 += x1; x1 = rotl32(x1, 15); x1 ^= x0;
    x0 += x1; x1 = rotl32(x1, 26); x1 ^= x0;
    x0 += x1; x1 = rotl32(x1, 6);  x1 ^= x0;
    x0 += k0; x1 += k1 + 3u;
    x0 += x1; x1 = rotl32(x1, 17); x1 ^= x0;
    x0 += x1; x1 = rotl32(x1, 29); x1 ^= x0;
    x0 += x1; x1 = rotl32(x1, 16); x1 ^= x0;
    x0 += x1; x1 = rotl32(x1, 24); x1 ^= x0;
    x0 += k1; x1 += k2 + 4u;
    x0 += x1; x1 = rotl32(x1, 13); x1 ^= x0;
    x0 += x1; x1 = rotl32(x1, 15); x1 ^= x0;
    x0 += x1; x1 = rotl32(x1, 26); x1 ^= x0;
    x0 += x1; x1 = rotl32(x1, 6);  x1 ^= x0;
    x0 += k2; x1 += k0 + 5u;
    o0 = x0; o1 = x1;
}

// ---------------- VQ top-10 + gumbel sample ----------------
__global__ void __launch_bounds__(256) vq_topk_sample() {
    int row = blockIdx.x, tid = threadIdx.x;
    const float* __restrict__ drow = g_dist + (size_t)row * Kc;
    float td[10]; int ti[10];
    #pragma unroll
    for (int j = 0; j < 10; j++) { td[j] = 3.4e38f; ti[j] = 0x7fffffff; }
    for (int c = tid; c < Kc; c += 256) {
        float v = drow[c];
        if (v < td[9] || (v == td[9] && c < ti[9])) {
            int pos = 9;
            #pragma unroll
            for (int j = 8; j >= 0; j--) {
                bool lt = (v < td[j]) || (v == td[j] && c < ti[j]);
                if (lt) pos = j;
            }
            #pragma unroll
            for (int j = 9; j > 0; j--)
                if (j > pos) { td[j] = td[j-1]; ti[j] = ti[j-1]; }
            td[pos] = v; ti[pos] = c;
        }
    }
    __shared__ float sd[2560];
    __shared__ int   si[2560];
    #pragma unroll
    for (int j = 0; j < 10; j++) { sd[tid * 10 + j] = td[j]; si[tid * 10 + j] = ti[j]; }
    for (int stride = 128; stride >= 1; stride >>= 1) {
        __syncthreads();
        if (tid < stride) {
            float od[10]; int oi[10];
            int a = 0, b2 = 0;
            #pragma unroll
            for (int j = 0; j < 10; j++) {
                float da = sd[tid * 10 + a], db = sd[(tid + stride) * 10 + b2];
                int   ia = si[tid * 10 + a], ib = si[(tid + stride) * 10 + b2];
                bool ta = (da < db) || (da == db && ia <= ib);
                if (ta) { od[j] = da; oi[j] = ia; a++; }
                else    { od[j] = db; oi[j] = ib; b2++; }
            }
            #pragma unroll
            for (int j = 0; j < 10; j++) { sd[tid * 10 + j] = od[j]; si[tid * 10 + j] = oi[j]; }
        }
    }
    __syncthreads();
    if (tid == 0) {
        float best = -3.4e38f;
        int bi = si[0];
        for (int j = 0; j < 10; j++) {
            uint32_t e = (uint32_t)(row * 10 + j);
            uint32_t o0, o1, bits;
#if JAX_PARTITIONABLE
            threefry2x32(0u, 42u, 0u, e, o0, o1);
            bits = o0 ^ o1;
#else
            if (e < 40960u) { threefry2x32(0u, 42u, e, e + 40960u, o0, o1); bits = o0; }
            else            { threefry2x32(0u, 42u, e - 40960u, e, o0, o1); bits = o1; }
#endif
            float u = __uint_as_float((bits >> 9) | 0x3f800000u) - 1.0f;
            u = u * 1.0f + 1e-10f;        // u*(maxval-minval)+minval
            u = fmaxf(1e-10f, u);
            float gmb = -logf(-logf(u));
            float sc = -sd[j] + gmb;      // neg_top/TEMP + gumbel, TEMP=1
            if (sc > best) { best = sc; bi = si[j]; }
        }
        g_enc[row] = bi;
    }
}

// ---------------- quantize: h = z_e + (codebook[enc] - z_e) ----------------
__global__ void __launch_bounds__(256) vq_quantize(const float* __restrict__ cb) {
    int row = blockIdx.x, tid = threadIdx.x;
    int e = g_enc[row];
    #pragma unroll
    for (int i = 0; i < 3; i++) {
        int c = tid + i * 256;
        float z = g_mem[(size_t)row * Dd + c];
        float q = cb[(size_t)e * Dd + c];
        g_h[(size_t)row * Dd + c] = z + (q - z);
    }
}

// ---------------- host ----------------
static void* sym(const void* devsym) {
    void* p = nullptr;
    cudaGetSymbolAddress(&p, devsym);
    return p;
}

extern "C" void kernel_launch(void* const* d_in, const int* in_sizes, int n_in,
                              void* d_out, int out_size) {
    const float* x       = (const float*)d_in[0];
    const float* cb      = (const float*)d_in[1];
    const float* sa_in_w = (const float*)d_in[2];
    const float* sa_in_b = (const float*)d_in[3];
    const float* sa_out_w= (const float*)d_in[4];
    const float* sa_out_b= (const float*)d_in[5];
    const float* ca_in_w = (const float*)d_in[6];
    const float* ca_in_b = (const float*)d_in[7];
    const float* ca_out_w= (const float*)d_in[8];
    const float* ca_out_b= (const float*)d_in[9];
    const float* ln1_g   = (const float*)d_in[10];
    const float* ln1_b   = (const float*)d_in[11];
    const float* ln2_g   = (const float*)d_in[12];
    const float* ln2_b   = (const float*)d_in[13];
    const float* ln3_g   = (const float*)d_in[14];
    const float* ln3_b   = (const float*)d_in[15];
    const float* ff_w1   = (const float*)d_in[16];
    const float* ff_b1   = (const float*)d_in[17];
    const float* ff_w2   = (const float*)d_in[18];
    const float* ff_b2   = (const float*)d_in[19];
    const float* out_w   = (const float*)d_in[20];
    const float* out_b   = (const float*)d_in[21];
    float* outp = (float*)d_out;

    float* p_mem   = (float*)sym(g_mem);
    float* p_h     = (float*)sym(g_h);
    float* p_tmp   = (float*)sym(g_tmp);
    float* p_attno = (float*)sym(g_attno);
    float* p_qkv   = (float*)sym(g_qkv);
    float* p_ff    = (float*)sym(g_ffbuf);
    float* p_dist  = (float*)sym(g_dist);
    float* p_xn    = (float*)sym(g_xnorm);
    float* p_cn    = (float*)sym(g_cnorm);

    auto GEMM = [](const float* A, int lda, const float* W, int ldw,
                   const float* bias, const float* resid, int ldr,
                   const float* rn, const float* cn,
                   float* C, int ldc, int M, int N, int K, int mode) {
        dim3 grid(N / 128, M / 128);
        sgemm_nt<<<grid, 256>>>(A, lda, W, ldw, bias, resid, ldr, rn, cn, C, ldc, K, mode);
    };

    // ---- VQ ----
    rowstat_x<<<NTOK, 256>>>(x);
    rowstat_cb<<<Kc, 256>>>(cb);
    GEMM(p_mem, Dd, cb, Dd, nullptr, nullptr, 0, p_xn, p_cn,
         p_dist, Kc, NTOK, Kc, Dd, 3);
    vq_topk_sample<<<NTOK, 256>>>();
    vq_quantize<<<NTOK, 256>>>(cb);

    // ---- decoder layers ----
    for (int l = 0; l < Ll; l++) {
        const float* siw = sa_in_w + (size_t)l * 3 * Dd * Dd;
        const float* sib = sa_in_b + (size_t)l * 3 * Dd;
        const float* sow = sa_out_w + (size_t)l * Dd * Dd;
        const float* sob = sa_out_b + (size_t)l * Dd;
        const float* ciw = ca_in_w + (size_t)l * 3 * Dd * Dd;
        const float* cib = ca_in_b + (size_t)l * 3 * Dd;
        const float* cow = ca_out_w + (size_t)l * Dd * Dd;
        const float* cob = ca_out_b + (size_t)l * Dd;

        // self-attention
        GEMM(p_h, Dd, siw, Dd, sib, nullptr, 0, nullptr, nullptr,
             p_qkv, 3 * Dd, NTOK, 3 * Dd, Dd, 0);
        attn_scores<<<dim3(8, 8, Bb * Hh), 256>>>(1);
        softmax512<<<Bb * Hh * Ss, 128>>>();
        attn_av<<<dim3(8, Bb * Hh), 256>>>();
        GEMM(p_attno, Dd, sow, Dd, sob, p_h, Dd, nullptr, nullptr,
             p_tmp, Dd, NTOK, Dd, Dd, 2);
        layernorm<<<NTOK, 256>>>(ln1_g + (size_t)l * Dd, ln1_b + (size_t)l * Dd);

        // cross-attention (q from h, k/v from mem)
        GEMM(p_h, Dd, ciw, Dd, cib, nullptr, 0, nullptr, nullptr,
             p_qkv, 3 * Dd, NTOK, Dd, Dd, 0);
        GEMM(p_mem, Dd, ciw + (size_t)Dd * Dd, Dd, cib + Dd, nullptr, 0, nullptr, nullptr,
             p_qkv + Dd, 3 * Dd, NTOK, 2 * Dd, Dd, 0);
        attn_scores<<<dim3(8, 8, Bb * Hh), 256>>>(0);
        softmax512<<<Bb * Hh * Ss, 128>>>();
        attn_av<<<dim3(8, Bb * Hh), 256>>>();
        GEMM(p_attno, Dd, cow, Dd, cob, p_h, Dd, nullptr, nullptr,
             p_tmp, Dd, NTOK, Dd, Dd, 2);
        layernorm<<<NTOK, 256>>>(ln2_g + (size_t)l * Dd, ln2_b + (size_t)l * Dd);

        // feed-forward
        GEMM(p_h, Dd, ff_w1 + (size_t)l * FFd * Dd, Dd, ff_b1 + (size_t)l * FFd,
             nullptr, 0, nullptr, nullptr, p_ff, FFd, NTOK, FFd, Dd, 1);
        GEMM(p_ff, FFd, ff_w2 + (size_t)l * Dd * FFd, FFd, ff_b2 + (size_t)l * Dd,
             p_h, Dd, nullptr, nullptr, p_tmp, Dd, NTOK, Dd, FFd, 2);
        layernorm<<<NTOK, 256>>>(ln3_g + (size_t)l * Dd, ln3_b + (size_t)l * Dd);
    }

    // ---- final projection ----
    GEMM(p_h, Dd, out_w, Dd, out_b, nullptr, 0, nullptr, nullptr,
         outp, Dd, NTOK, Dd, Dd, 0);
}